// round 9
// baseline (speedup 1.0000x reference)
#include <cuda_runtime.h>
#include <cuda_fp16.h>
#include <math.h>
#include <stdint.h>

// ---------------------------------------------------------------------------
// Problem constants
// ---------------------------------------------------------------------------
#define CSZ     512
#define MROWS   131072      // H*W*B = 4096*32

// ---------------------------------------------------------------------------
// Scratch (static device globals -- no allocations allowed)
// ---------------------------------------------------------------------------
__device__ __half g_xw    [(size_t)MROWS * CSZ];    // LN1 out, A-frag half (kT=16)
__device__ __half g_ctx   [(size_t)MROWS * CSZ];    // attn out, A-frag half (kT=16)
__device__ float  g_hidden[(size_t)MROWS * CSZ];    // post-attn residual, row-major fp32
__device__ __half g_ln2   [(size_t)MROWS * CSZ];    // LN2 out, A-frag half (kT=16)
__device__ __half g_big   [(size_t)MROWS * 2048];   // qkv row-major half(1536); fc1-out frag (kT=64)
__device__ __half g_wprep [512*1536 + 512*512 + 512*2048 + 2048*512];

#define WP_QKV  0
#define WP_PROJ (512*1536)
#define WP_FC1  (WP_PROJ + 512*512)
#define WP_FC2  (WP_FC1 + 512*2048)

// ---------------------------------------------------------------------------
// Helpers
// ---------------------------------------------------------------------------
__device__ __forceinline__ uint32_t smem_u32(const void* p) {
    uint32_t a;
    asm("{ .reg .u64 t; cvta.to.shared.u64 t, %1; cvt.u32.u64 %0, t; }" : "=r"(a) : "l"(p));
    return a;
}
__device__ __forceinline__ uint32_t pack_half2(float lo, float hi) {
    __half2 h = __floats2half2_rn(lo, hi);       // .x = lo (low 16), .y = hi (high 16)
    return *reinterpret_cast<uint32_t*>(&h);     // full 32-bit pattern
}
__device__ __forceinline__ void mma_f16(float* d, uint32_t a0, uint32_t a1, uint32_t a2, uint32_t a3,
                                        uint32_t b0, uint32_t b1)
{
    asm volatile(
        "mma.sync.aligned.m16n8k16.row.col.f32.f16.f16.f32 "
        "{%0,%1,%2,%3}, {%4,%5,%6,%7}, {%8,%9}, {%0,%1,%2,%3};"
        : "+f"(d[0]), "+f"(d[1]), "+f"(d[2]), "+f"(d[3])
        : "r"(a0), "r"(a1), "r"(a2), "r"(a3), "r"(b0), "r"(b1));
}
__device__ __forceinline__ void cp_async16(uint32_t dst, const void* src) {
    asm volatile("cp.async.cg.shared.global [%0], [%1], 16;" :: "r"(dst), "l"(src) : "memory");
}
#define CP_COMMIT() asm volatile("cp.async.commit_group;" ::: "memory")
#define CP_WAIT(n)  asm volatile("cp.async.wait_group %0;" :: "n"(n) : "memory")

__device__ __forceinline__ float gelu_exact(float x)
{
    return 0.5f * x * (1.0f + erff(x * 0.70710678118654752f));
}

// Half A-fragment address (half index) for element (row r, channel c), kT chunks.
__device__ __forceinline__ size_t fragAddrH(long r, int c, int kT) {
    int rm = (int)(r & 255);
    int ri = rm & 15;
    int k  = c & 31;
    return ((size_t)(r >> 8) * kT + (c >> 5)) * 8192
         + (size_t)(((((rm >> 4) * 2 + (k >> 4)) * 32) + (ri & 7) * 4 + ((k >> 1) & 3)) * 8
         + ((k >> 3) & 1) * 4 + (ri >> 3) * 2 + (k & 1));
}

// ---------------------------------------------------------------------------
// Weight prep: W[K,N] fp32 row-major -> per (ntile j, kchunk kt) 4096-half B-frag
// ---------------------------------------------------------------------------
__global__ __launch_bounds__(256) void k_prep(const float* __restrict__ W,
                                              __half* __restrict__ dst,
                                              int N, int kTiles)
{
    int j = blockIdx.x, kt = blockIdx.y;
    __half* blk = dst + ((size_t)(j * kTiles + kt)) * 4096;
    for (int f = threadIdx.x; f < 4096; f += 256) {
        int klo = f & 1;
        int reg = (f >> 1) & 3;
        int lanep = (f >> 3) & 31;
        int q = lanep & 3, g = lanep >> 2;
        int nt = f >> 8;
        int n_local = nt * 8 + g;
        int k_local = reg * 8 + q * 2 + klo;
        blk[f] = __float2half_rn(W[(size_t)(kt * 32 + k_local) * N + j * 128 + n_local]);
    }
}

// ---------------------------------------------------------------------------
// LayerNorm (+ optional shift/window-partition gather); writes half A-frag (kT=16)
// ---------------------------------------------------------------------------
__global__ __launch_bounds__(128) void k_ln(const float* __restrict__ x,
                                            const float* __restrict__ g,
                                            const float* __restrict__ b,
                                            __half* __restrict__ y,
                                            int permute)
{
    long r = blockIdx.x;
    long src = r;
    if (permute) {
        int s  = (int)(r >> 11), n = (int)(r & 2047);
        int hn = s >> 3, wn = s & 7;
        int ij = n >> 5, bb = n & 31;
        int h  = ((hn << 3) + (ij >> 3) + 4) & 63;
        int w  = ((wn << 3) + (ij & 7) + 4) & 63;
        src = ((h << 6) + w) * 32 + bb;
    }
    int t = threadIdx.x;
    float4 v = ((const float4*)(x + src * CSZ))[t];
    float sum = v.x + v.y + v.z + v.w;
    float sq  = v.x*v.x + v.y*v.y + v.z*v.z + v.w*v.w;
    #pragma unroll
    for (int o = 16; o > 0; o >>= 1) {
        sum += __shfl_xor_sync(0xffffffffu, sum, o);
        sq  += __shfl_xor_sync(0xffffffffu, sq,  o);
    }
    __shared__ float ssum[4], ssq[4];
    int warp = t >> 5, lane = t & 31;
    if (lane == 0) { ssum[warp] = sum; ssq[warp] = sq; }
    __syncthreads();
    float tot = ssum[0] + ssum[1] + ssum[2] + ssum[3];
    float tq  = ssq[0]  + ssq[1]  + ssq[2]  + ssq[3];
    float mu  = tot * (1.0f / 512.0f);
    float var = tq * (1.0f / 512.0f) - mu * mu;
    float inv = rsqrtf(var + 1e-5f);
    float4 gg = ((const float4*)g)[t];
    float4 bb4 = ((const float4*)b)[t];
    float o0 = (v.x - mu) * inv * gg.x + bb4.x;
    float o1 = (v.y - mu) * inv * gg.y + bb4.y;
    float o2 = (v.z - mu) * inv * gg.z + bb4.z;
    float o3 = (v.w - mu) * inv * gg.w + bb4.w;

    size_t a0 = fragAddrH(r, 4 * t, 16);
    size_t a1 = fragAddrH(r, 4 * t + 2, 16);
    *(__half2*)&y[a0] = __floats2half2_rn(o0, o1);
    *(__half2*)&y[a1] = __floats2half2_rn(o2, o3);
}

// ---------------------------------------------------------------------------
// Tensor-core windowed attention. One block per n (0..2047), 8 warps.
// Warp w handles heads w and w+8 in warp-private smem (12KB):
//   Q in A-frag order, K in B-frag order (k=channel), V^T in B-frag order (k=t).
// ---------------------------------------------------------------------------
__device__ __forceinline__ int regcode(int h) { return h < 56 ? 0 : (h < 60 ? 1 : 2); }

#define ATTN_SMEM 98304   // 8 warps * 12KB

__global__ __launch_bounds__(256) void k_attn(const __half* __restrict__ qkv,
                                              __half* __restrict__ ctx)
{
    extern __shared__ char smem[];
    const uint32_t sbase = smem_u32(smem);
    const int n    = blockIdx.x;
    const int tid  = threadIdx.x;
    const int wid  = tid >> 5;
    const int lane = tid & 31;
    const int g    = lane >> 2;
    const int q    = lane & 3;
    const int nw   = n & 63;

    const uint32_t wQ = sbase + (uint32_t)wid * 12288;          // bytes
    const uint32_t wK = wQ + 4096;
    const uint32_t wV = wQ + 8192;

    const int hn8 = (nw >> 3) << 3;
    const int wn8 = (nw & 7) << 3;

    for (int hh = 0; hh < 2; hh++) {
        const int hd = wid + hh * 8;

        // ---- load Q,K,V for (n, hd) into warp smem frag layouts ----
        #pragma unroll
        for (int i = 0; i < 8; i++) {
            int idx = i * 32 + lane;           // 0..255
            int s  = idx >> 2;                 // row 0..63
            int c8 = idx & 3;                  // 8-half chunk of 32 channels
            const __half* src = qkv + ((size_t)(s * 2048 + n)) * 1536 + hd * 96 + c8 * 8;
            uint4 uq = *(const uint4*)(src);
            uint4 uk = *(const uint4*)(src + 32);
            uint4 uv = *(const uint4*)(src + 64);

            // Q -> A-frag: tile (mi*2 + kt2)*256 halves
            {
                int mi = s >> 4, rm = s & 15;
                int g2 = rm & 7, hi = rm >> 3;
                int kt2 = c8 >> 1, khi = c8 & 1;
                uint32_t base = wQ + ((uint32_t)((mi * 2 + kt2) * 256 + g2 * 32 + khi * 4 + hi * 2)) * 2;
                asm volatile("st.shared.b32 [%0], %1;" :: "r"(base +  0), "r"(uq.x) : "memory");
                asm volatile("st.shared.b32 [%0], %1;" :: "r"(base + 16), "r"(uq.y) : "memory");
                asm volatile("st.shared.b32 [%0], %1;" :: "r"(base + 32), "r"(uq.z) : "memory");
                asm volatile("st.shared.b32 [%0], %1;" :: "r"(base + 48), "r"(uq.w) : "memory");
            }
            // K -> B-frag: n=t=s, k=channel. Consecutive channel pairs -> +1 lane (+16B).
            {
                int nt = s >> 3, g2 = s & 7;
                uint32_t base = wK + ((uint32_t)((nt * 32 + g2 * 4) * 8 + c8 * 2)) * 2;
                asm volatile("st.shared.b32 [%0], %1;" :: "r"(base +  0), "r"(uk.x) : "memory");
                asm volatile("st.shared.b32 [%0], %1;" :: "r"(base + 16), "r"(uk.y) : "memory");
                asm volatile("st.shared.b32 [%0], %1;" :: "r"(base + 32), "r"(uk.z) : "memory");
                asm volatile("st.shared.b32 [%0], %1;" :: "r"(base + 48), "r"(uk.w) : "memory");
            }
            // V -> B-frag transposed: n=d, k=t
            {
                int t5 = s & 31, kc = s >> 5;
                int reg = t5 >> 3, qp = (t5 >> 1) & 3, klo = t5 & 1;
                uint32_t h8[8];
                h8[0] = uv.x & 0xffffu; h8[1] = uv.x >> 16;
                h8[2] = uv.y & 0xffffu; h8[3] = uv.y >> 16;
                h8[4] = uv.z & 0xffffu; h8[5] = uv.z >> 16;
                h8[6] = uv.w & 0xffffu; h8[7] = uv.w >> 16;
                #pragma unroll
                for (int dj = 0; dj < 8; dj++) {
                    uint32_t a = wV + ((uint32_t)(((kc * 4 + c8) * 32 + dj * 4 + qp) * 8 + reg * 2 + klo)) * 2;
                    asm volatile("st.shared.u16 [%0], %1;" :: "r"(a), "r"(h8[dj]) : "memory");
                }
            }
        }
        __syncwarp();

        // ---- V fragments (held across mi loop): vf[ntd][kc][reg] ----
        uint32_t vf[4][2][4];
        #pragma unroll
        for (int ntd = 0; ntd < 4; ntd++)
            #pragma unroll
            for (int kc = 0; kc < 2; kc++) {
                uint32_t addr = wV + ((uint32_t)(((kc * 4 + ntd) * 32 + lane) * 8)) * 2;
                asm volatile("ld.shared.v4.b32 {%0,%1,%2,%3}, [%4];"
                             : "=r"(vf[ntd][kc][0]), "=r"(vf[ntd][kc][1]),
                               "=r"(vf[ntd][kc][2]), "=r"(vf[ntd][kc][3])
                             : "r"(addr));
            }

        #pragma unroll
        for (int mi = 0; mi < 4; mi++) {
            // Q frags for this 16-row band (both k16 tiles)
            uint32_t aq[2][4];
            #pragma unroll
            for (int kt2 = 0; kt2 < 2; kt2++) {
                uint32_t addr = wQ + ((uint32_t)(((mi * 2 + kt2) * 32 + lane) * 8)) * 2;
                asm volatile("ld.shared.v4.b32 {%0,%1,%2,%3}, [%4];"
                             : "=r"(aq[kt2][0]), "=r"(aq[kt2][1]), "=r"(aq[kt2][2]), "=r"(aq[kt2][3])
                             : "r"(addr));
            }
            // S = Q K^T
            float sc[8][4];
            #pragma unroll
            for (int nt = 0; nt < 8; nt++) {
                sc[nt][0] = sc[nt][1] = sc[nt][2] = sc[nt][3] = 0.0f;
                uint32_t bk[4];
                uint32_t addr = wK + ((uint32_t)((nt * 32 + lane) * 8)) * 2;
                asm volatile("ld.shared.v4.b32 {%0,%1,%2,%3}, [%4];"
                             : "=r"(bk[0]), "=r"(bk[1]), "=r"(bk[2]), "=r"(bk[3]) : "r"(addr));
                mma_f16(sc[nt], aq[0][0], aq[0][1], aq[0][2], aq[0][3], bk[0], bk[1]);
                mma_f16(sc[nt], aq[1][0], aq[1][1], aq[1][2], aq[1][3], bk[2], bk[3]);
            }

            // ---- scale + mask + softmax (rows r0 = mi*16+g, r1 = r0+8) ----
            const int r0 = mi * 16 + g, r1 = r0 + 8;
            const int cs0 = regcode(hn8 + (r0 >> 3)) * 3 + regcode(wn8 + (r0 & 7));
            const int cs1 = regcode(hn8 + (r1 >> 3)) * 3 + regcode(wn8 + (r1 & 7));
            const float scale = 0.17677669529663689f;

            float mx0 = -1e30f, mx1 = -1e30f;
            #pragma unroll
            for (int nt = 0; nt < 8; nt++) {
                int c0 = nt * 8 + q * 2, c1 = c0 + 1;
                int ct0 = regcode(hn8 + (c0 >> 3)) * 3 + regcode(wn8 + (c0 & 7));
                int ct1 = regcode(hn8 + (c1 >> 3)) * 3 + regcode(wn8 + (c1 & 7));
                sc[nt][0] = (ct0 != cs0) ? -10000.0f : sc[nt][0] * scale;
                sc[nt][1] = (ct1 != cs0) ? -10000.0f : sc[nt][1] * scale;
                sc[nt][2] = (ct0 != cs1) ? -10000.0f : sc[nt][2] * scale;
                sc[nt][3] = (ct1 != cs1) ? -10000.0f : sc[nt][3] * scale;
                mx0 = fmaxf(mx0, fmaxf(sc[nt][0], sc[nt][1]));
                mx1 = fmaxf(mx1, fmaxf(sc[nt][2], sc[nt][3]));
            }
            mx0 = fmaxf(mx0, __shfl_xor_sync(0xffffffffu, mx0, 1));
            mx0 = fmaxf(mx0, __shfl_xor_sync(0xffffffffu, mx0, 2));
            mx1 = fmaxf(mx1, __shfl_xor_sync(0xffffffffu, mx1, 1));
            mx1 = fmaxf(mx1, __shfl_xor_sync(0xffffffffu, mx1, 2));

            float sm0 = 0.0f, sm1 = 0.0f;
            #pragma unroll
            for (int nt = 0; nt < 8; nt++) {
                sc[nt][0] = __expf(sc[nt][0] - mx0);
                sc[nt][1] = __expf(sc[nt][1] - mx0);
                sc[nt][2] = __expf(sc[nt][2] - mx1);
                sc[nt][3] = __expf(sc[nt][3] - mx1);
                sm0 += sc[nt][0] + sc[nt][1];
                sm1 += sc[nt][2] + sc[nt][3];
            }
            sm0 += __shfl_xor_sync(0xffffffffu, sm0, 1);
            sm0 += __shfl_xor_sync(0xffffffffu, sm0, 2);
            sm1 += __shfl_xor_sync(0xffffffffu, sm1, 1);
            sm1 += __shfl_xor_sync(0xffffffffu, sm1, 2);

            // ---- P (A-frag refit, FULL 32-bit packs) x V ----
            uint32_t pa[4][4];
            #pragma unroll
            for (int kt = 0; kt < 4; kt++) {
                pa[kt][0] = pack_half2(sc[2*kt][0],   sc[2*kt][1]);
                pa[kt][1] = pack_half2(sc[2*kt][2],   sc[2*kt][3]);
                pa[kt][2] = pack_half2(sc[2*kt+1][0], sc[2*kt+1][1]);
                pa[kt][3] = pack_half2(sc[2*kt+1][2], sc[2*kt+1][3]);
            }
            float o[4][4];
            #pragma unroll
            for (int ntd = 0; ntd < 4; ntd++) o[ntd][0] = o[ntd][1] = o[ntd][2] = o[ntd][3] = 0.0f;
            #pragma unroll
            for (int kt = 0; kt < 4; kt++) {
                int kc = kt >> 1, sub = kt & 1;
                #pragma unroll
                for (int ntd = 0; ntd < 4; ntd++)
                    mma_f16(o[ntd], pa[kt][0], pa[kt][1], pa[kt][2], pa[kt][3],
                            vf[ntd][kc][sub * 2], vf[ntd][kc][sub * 2 + 1]);
            }

            // ---- normalize + write ctx (A-frag layout, kT=16) ----
            float inv0 = 1.0f / sm0, inv1 = 1.0f / sm1;
            long rg0 = (long)r0 * 2048 + n;
            long rg1 = (long)r1 * 2048 + n;
            #pragma unroll
            for (int ntd = 0; ntd < 4; ntd++) {
                int c = hd * 32 + ntd * 8 + q * 2;
                size_t a0 = fragAddrH(rg0, c, 16);
                size_t a1 = fragAddrH(rg1, c, 16);
                *(__half2*)&ctx[a0] = __floats2half2_rn(o[ntd][0] * inv0, o[ntd][1] * inv0);
                *(__half2*)&ctx[a1] = __floats2half2_rn(o[ntd][2] * inv1, o[ntd][3] * inv1);
            }
        }
        __syncwarp();
    }
}

// ---------------------------------------------------------------------------
// fp16 mma.sync GEMM: CTA tile 256x128, chunk K=32, 8 warps (4m x 2n) of 64x64.
// ---------------------------------------------------------------------------
#define NSTAGE     4
#define STAGE_B    24576                 // 16KB A + 8KB B
#define DYN_SMEM   (NSTAGE * STAGE_B)    // 98304

template <int EPI>
__global__ __launch_bounds__(256, 1) void gemm_tc(const __half* __restrict__ A,
                                                  const __half* __restrict__ Bprep,
                                                  const float* __restrict__ bias,
                                                  void* __restrict__ Cout,
                                                  const void* __restrict__ add1,
                                                  const void* __restrict__ add2,
                                                  int Nout, int kTiles)
{
    extern __shared__ char smem[];
    const uint32_t sbase = smem_u32(smem);
    const int tid  = threadIdx.x;
    const int wid  = tid >> 5;
    const int lane = tid & 31;
    const int wm   = wid >> 1;
    const int wnb  = wid & 1;

    const long rowBlk = (long)blockIdx.y * 256;
    const int  colBlk = blockIdx.x * 128;
    const __half* Ablk = A + (size_t)blockIdx.y * kTiles * 8192;
    const __half* Bblk = Bprep + (size_t)blockIdx.x * kTiles * 4096;

    float acc[4][8][4];
    #pragma unroll
    for (int mi = 0; mi < 4; mi++)
        #pragma unroll
        for (int nt = 0; nt < 8; nt++)
            #pragma unroll
            for (int j = 0; j < 4; j++) acc[mi][nt][j] = 0.0f;

    auto issue = [&](int kt) {
        uint32_t aB = sbase + (kt % NSTAGE) * STAGE_B;
        uint32_t bB = aB + 16384;
        const __half* as = Ablk + (size_t)kt * 8192;
        const __half* bs = Bblk + (size_t)kt * 4096;
        #pragma unroll
        for (int i = 0; i < 4; i++)
            cp_async16(aB + (uint32_t)(tid + i * 256) * 16, as + (size_t)(tid + i * 256) * 8);
        #pragma unroll
        for (int i = 0; i < 2; i++)
            cp_async16(bB + (uint32_t)(tid + i * 256) * 16, bs + (size_t)(tid + i * 256) * 8);
        CP_COMMIT();
    };

    issue(0); issue(1); issue(2);

    for (int kt = 0; kt < kTiles; kt++) {
        if (kt < kTiles - 2)      { CP_WAIT(2); }
        else if (kt == kTiles - 2){ CP_WAIT(1); }
        else                      { CP_WAIT(0); }
        __syncthreads();
        if (kt + 3 < kTiles) issue(kt + 3);

        const uint32_t aB = sbase + (kt % NSTAGE) * STAGE_B;
        const uint32_t bB = aB + 16384;

        uint32_t bfr[8][4];
        #pragma unroll
        for (int nt = 0; nt < 8; nt++) {
            uint32_t addr = bB + (uint32_t)(((wnb * 8 + nt) * 32 + lane) * 16);
            asm volatile("ld.shared.v4.b32 {%0,%1,%2,%3}, [%4];"
                         : "=r"(bfr[nt][0]), "=r"(bfr[nt][1]), "=r"(bfr[nt][2]), "=r"(bfr[nt][3])
                         : "r"(addr));
        }
        #pragma unroll
        for (int ks2 = 0; ks2 < 2; ks2++) {
            uint32_t afr[4][4];
            #pragma unroll
            for (int mi = 0; mi < 4; mi++) {
                uint32_t addr = aB + (uint32_t)((((wm * 4 + mi) * 2 + ks2) * 32 + lane) * 16);
                asm volatile("ld.shared.v4.b32 {%0,%1,%2,%3}, [%4];"
                             : "=r"(afr[mi][0]), "=r"(afr[mi][1]), "=r"(afr[mi][2]), "=r"(afr[mi][3])
                             : "r"(addr));
            }
            #pragma unroll
            for (int mi = 0; mi < 4; mi++)
                #pragma unroll
                for (int nt = 0; nt < 8; nt++)
                    mma_f16(acc[mi][nt], afr[mi][0], afr[mi][1], afr[mi][2], afr[mi][3],
                            bfr[nt][ks2 * 2], bfr[nt][ks2 * 2 + 1]);
        }
    }

    const int g  = lane >> 2;
    const int q2 = lane & 3;

    float2 bs2[8];
    #pragma unroll
    for (int nt = 0; nt < 8; nt++)
        bs2[nt] = *(const float2*)&bias[colBlk + wnb * 64 + nt * 8 + q2 * 2];

    #pragma unroll
    for (int mi = 0; mi < 4; mi++) {
        long r = rowBlk + wm * 64 + mi * 16 + g;

        long d0 = 0, d1 = 0;
        if (EPI == 1) {
            {
                int s = (int)(r >> 11), n = (int)(r & 2047);
                int hn = s >> 3, wn2 = s & 7;
                int ij = n >> 5, b2 = n & 31;
                int h = ((hn << 3) + (ij >> 3) + 4) & 63;
                int w = ((wn2 << 3) + (ij & 7) + 4) & 63;
                d0 = ((long)(((h << 6) + w) * 32 + b2)) * 512;
            }
            {
                long r8 = r + 8;
                int s = (int)(r8 >> 11), n = (int)(r8 & 2047);
                int hn = s >> 3, wn2 = s & 7;
                int ij = n >> 5, b2 = n & 31;
                int h = ((hn << 3) + (ij >> 3) + 4) & 63;
                int w = ((wn2 << 3) + (ij & 7) + 4) & 63;
                d1 = ((long)(((h << 6) + w) * 32 + b2)) * 512;
            }
        }

        #pragma unroll
        for (int nt = 0; nt < 8; nt++) {
            int c = colBlk + wnb * 64 + nt * 8 + q2 * 2;
            float v00 = acc[mi][nt][0] + bs2[nt].x;
            float v01 = acc[mi][nt][1] + bs2[nt].y;
            float v10 = acc[mi][nt][2] + bs2[nt].x;
            float v11 = acc[mi][nt][3] + bs2[nt].y;

            if (EPI == 0) {
                __half* Ch = (__half*)Cout;
                *(__half2*)&Ch[r * Nout + c]       = __floats2half2_rn(v00, v01);
                *(__half2*)&Ch[(r + 8) * Nout + c] = __floats2half2_rn(v10, v11);
            } else if (EPI == 1) {
                float* Cf = (float*)Cout;
                const __half* xwH = (const __half*)add1;
                const float*  hsF = (const float*)add2;
                size_t a = fragAddrH(r, c, 16);
                float2 x01 = __half22float2(*(const __half2*)&xwH[a]);
                float2 x89 = __half22float2(*(const __half2*)&xwH[a + 2]);
                float2 s0 = *(const float2*)&hsF[d0 + c];
                float2 s1 = *(const float2*)&hsF[d1 + c];
                v00 += x01.x + s0.x; v01 += x01.y + s0.y;
                v10 += x89.x + s1.x; v11 += x89.y + s1.y;
                *(float2*)&Cf[d0 + c] = make_float2(v00, v01);
                *(float2*)&Cf[d1 + c] = make_float2(v10, v11);
            } else if (EPI == 2) {
                __half* Ch = (__half*)Cout;
                size_t a = fragAddrH(r, c, 64);
                *(__half2*)&Ch[a]     = __floats2half2_rn(gelu_exact(v00), gelu_exact(v01));
                *(__half2*)&Ch[a + 2] = __floats2half2_rn(gelu_exact(v10), gelu_exact(v11));
            } else {
                float* Cf = (float*)Cout;
                const float*  hF  = (const float*)add1;
                const __half* lnH = (const __half*)add2;
                size_t a = fragAddrH(r, c, 16);
                float2 l01 = __half22float2(*(const __half2*)&lnH[a]);
                float2 l89 = __half22float2(*(const __half2*)&lnH[a + 2]);
                float2 h0 = *(const float2*)&hF[r * 512 + c];
                float2 h1 = *(const float2*)&hF[(r + 8) * 512 + c];
                v00 += h0.x + l01.x; v01 += h0.y + l01.y;
                v10 += h1.x + l89.x; v11 += h1.y + l89.y;
                *(float2*)&Cf[r * 512 + c]       = make_float2(v00, v01);
                *(float2*)&Cf[(r + 8) * 512 + c] = make_float2(v10, v11);
            }
        }
    }
}

// ---------------------------------------------------------------------------
// Launcher
// ---------------------------------------------------------------------------
extern "C" void kernel_launch(void* const* d_in, const int* in_sizes, int n_in,
                              void* d_out, int out_size)
{
    const float* hs    = (const float*)d_in[0];
    const float* ln1g  = (const float*)d_in[1];
    const float* ln1b  = (const float*)d_in[2];
    const float* wqkv  = (const float*)d_in[3];
    const float* bqkv  = (const float*)d_in[4];
    const float* wproj = (const float*)d_in[5];
    const float* bproj = (const float*)d_in[6];
    const float* ln2g  = (const float*)d_in[7];
    const float* ln2b  = (const float*)d_in[8];
    const float* wfc1  = (const float*)d_in[9];
    const float* bfc1  = (const float*)d_in[10];
    const float* wfc2  = (const float*)d_in[11];
    const float* bfc2  = (const float*)d_in[12];
    float* out = (float*)d_out;

    __half *xw, *ctx, *ln2buf, *big, *wprep;
    float *hidden;
    cudaGetSymbolAddress((void**)&xw,     g_xw);
    cudaGetSymbolAddress((void**)&ctx,    g_ctx);
    cudaGetSymbolAddress((void**)&hidden, g_hidden);
    cudaGetSymbolAddress((void**)&ln2buf, g_ln2);
    cudaGetSymbolAddress((void**)&big,    g_big);
    cudaGetSymbolAddress((void**)&wprep,  g_wprep);

    static int smem_set = 0;
    if (!smem_set) {
        cudaFuncSetAttribute(gemm_tc<0>, cudaFuncAttributeMaxDynamicSharedMemorySize, DYN_SMEM);
        cudaFuncSetAttribute(gemm_tc<1>, cudaFuncAttributeMaxDynamicSharedMemorySize, DYN_SMEM);
        cudaFuncSetAttribute(gemm_tc<2>, cudaFuncAttributeMaxDynamicSharedMemorySize, DYN_SMEM);
        cudaFuncSetAttribute(gemm_tc<3>, cudaFuncAttributeMaxDynamicSharedMemorySize, DYN_SMEM);
        cudaFuncSetAttribute(k_attn,     cudaFuncAttributeMaxDynamicSharedMemorySize, ATTN_SMEM);
        smem_set = 1;
    }

    // 0) preformat weights into half B-fragment blocks
    k_prep<<<dim3(12, 16), 256>>>(wqkv,  wprep + WP_QKV,  1536, 16);
    k_prep<<<dim3(4,  16), 256>>>(wproj, wprep + WP_PROJ, 512,  16);
    k_prep<<<dim3(16, 16), 256>>>(wfc1,  wprep + WP_FC1,  2048, 16);
    k_prep<<<dim3(4,  64), 256>>>(wfc2,  wprep + WP_FC2,  512,  64);

    // 1) LN1 + shift + window partition -> xw (half frag)
    k_ln<<<MROWS, 128>>>(hs, ln1g, ln1b, xw, 1);

    // 2) QKV GEMM -> big (half row-major, 1536)
    gemm_tc<0><<<dim3(12, 512), 256, DYN_SMEM>>>(xw, wprep + WP_QKV, bqkv, big,
                                                 nullptr, nullptr, 1536, 16);

    // 3) Windowed attention (tensor core) -> ctx (half frag)
    k_attn<<<2048, 256, ATTN_SMEM>>>(big, ctx);

    // 4) Proj GEMM + residual + window-reverse scatter -> hidden (fp32 row-major)
    gemm_tc<1><<<dim3(4, 512), 256, DYN_SMEM>>>(ctx, wprep + WP_PROJ, bproj, hidden,
                                                xw, hs, 512, 16);

    // 5) LN2 -> ln2buf (half frag)
    k_ln<<<MROWS, 128>>>(hidden, ln2g, ln2b, ln2buf, 0);

    // 6) FC1 GEMM + GELU -> big (half frag, kT=64)
    gemm_tc<2><<<dim3(16, 512), 256, DYN_SMEM>>>(ln2buf, wprep + WP_FC1, bfc1, big,
                                                 nullptr, nullptr, 2048, 16);

    // 7) FC2 GEMM + final residuals -> out (fp32 row-major)
    gemm_tc<3><<<dim3(4, 512), 256, DYN_SMEM>>>(big, wprep + WP_FC2, bfc2, out,
                                                hidden, ln2buf, 512, 64);
}

// round 11
// speedup vs baseline: 1.2340x; 1.2340x over previous
#include <cuda_runtime.h>
#include <cuda_fp16.h>
#include <math.h>
#include <stdint.h>

// ---------------------------------------------------------------------------
// Problem constants
// ---------------------------------------------------------------------------
#define CSZ     512
#define MROWS   131072      // H*W*B = 4096*32

// ---------------------------------------------------------------------------
// Scratch (static device globals -- no allocations allowed)
// ---------------------------------------------------------------------------
__device__ __half g_xw    [(size_t)MROWS * CSZ];    // LN1 out, A-frag half (kT=16)
__device__ __half g_ctx   [(size_t)MROWS * CSZ];    // attn out, A-frag half (kT=16)
__device__ float  g_hidden[(size_t)MROWS * CSZ];    // post-attn residual, row-major fp32
__device__ __half g_ln2   [(size_t)MROWS * CSZ];    // LN2 out, A-frag half (kT=16)
__device__ __half g_big   [(size_t)MROWS * 2048];   // qkv row-major half(1536); fc1-out frag (kT=64)
__device__ __half g_wprep [512*1536 + 512*512 + 512*2048 + 2048*512];

#define WP_QKV  0
#define WP_PROJ (512*1536)
#define WP_FC1  (WP_PROJ + 512*512)
#define WP_FC2  (WP_FC1 + 512*2048)

// ---------------------------------------------------------------------------
// Helpers
// ---------------------------------------------------------------------------
__device__ __forceinline__ uint32_t smem_u32(const void* p) {
    uint32_t a;
    asm("{ .reg .u64 t; cvta.to.shared.u64 t, %1; cvt.u32.u64 %0, t; }" : "=r"(a) : "l"(p));
    return a;
}
__device__ __forceinline__ void mma_f16(float* d, uint32_t a0, uint32_t a1, uint32_t a2, uint32_t a3,
                                        uint32_t b0, uint32_t b1)
{
    asm volatile(
        "mma.sync.aligned.m16n8k16.row.col.f32.f16.f16.f32 "
        "{%0,%1,%2,%3}, {%4,%5,%6,%7}, {%8,%9}, {%0,%1,%2,%3};"
        : "+f"(d[0]), "+f"(d[1]), "+f"(d[2]), "+f"(d[3])
        : "r"(a0), "r"(a1), "r"(a2), "r"(a3), "r"(b0), "r"(b1));
}
__device__ __forceinline__ void cp_async16(uint32_t dst, const void* src) {
    asm volatile("cp.async.cg.shared.global [%0], [%1], 16;" :: "r"(dst), "l"(src) : "memory");
}
#define CP_COMMIT() asm volatile("cp.async.commit_group;" ::: "memory")
#define CP_WAIT(n)  asm volatile("cp.async.wait_group %0;" :: "n"(n) : "memory")

__device__ __forceinline__ float gelu_exact(float x)
{
    return 0.5f * x * (1.0f + erff(x * 0.70710678118654752f));
}

// Half A-fragment address (half index) for element (row r, channel c), kT chunks.
__device__ __forceinline__ size_t fragAddrH(long r, int c, int kT) {
    int rm = (int)(r & 255);
    int ri = rm & 15;
    int k  = c & 31;
    return ((size_t)(r >> 8) * kT + (c >> 5)) * 8192
         + (size_t)(((((rm >> 4) * 2 + (k >> 4)) * 32) + (ri & 7) * 4 + ((k >> 1) & 3)) * 8
         + ((k >> 3) & 1) * 4 + (ri >> 3) * 2 + (k & 1));
}

// ---------------------------------------------------------------------------
// Weight prep: W[K,N] fp32 row-major -> per (ntile j, kchunk kt) 4096-half B-frag
// ---------------------------------------------------------------------------
__global__ __launch_bounds__(256) void k_prep(const float* __restrict__ W,
                                              __half* __restrict__ dst,
                                              int N, int kTiles)
{
    int j = blockIdx.x, kt = blockIdx.y;
    __half* blk = dst + ((size_t)(j * kTiles + kt)) * 4096;
    for (int f = threadIdx.x; f < 4096; f += 256) {
        int klo = f & 1;
        int reg = (f >> 1) & 3;
        int lanep = (f >> 3) & 31;
        int q = lanep & 3, g = lanep >> 2;
        int nt = f >> 8;
        int n_local = nt * 8 + g;
        int k_local = reg * 8 + q * 2 + klo;
        blk[f] = __float2half_rn(W[(size_t)(kt * 32 + k_local) * N + j * 128 + n_local]);
    }
}

// ---------------------------------------------------------------------------
// LayerNorm (+ optional shift/window-partition gather); writes half A-frag (kT=16)
// ---------------------------------------------------------------------------
__global__ __launch_bounds__(128) void k_ln(const float* __restrict__ x,
                                            const float* __restrict__ g,
                                            const float* __restrict__ b,
                                            __half* __restrict__ y,
                                            int permute)
{
    long r = blockIdx.x;
    long src = r;
    if (permute) {
        int s  = (int)(r >> 11), n = (int)(r & 2047);
        int hn = s >> 3, wn = s & 7;
        int ij = n >> 5, bb = n & 31;
        int h  = ((hn << 3) + (ij >> 3) + 4) & 63;
        int w  = ((wn << 3) + (ij & 7) + 4) & 63;
        src = ((h << 6) + w) * 32 + bb;
    }
    int t = threadIdx.x;
    float4 v = ((const float4*)(x + src * CSZ))[t];
    float sum = v.x + v.y + v.z + v.w;
    float sq  = v.x*v.x + v.y*v.y + v.z*v.z + v.w*v.w;
    #pragma unroll
    for (int o = 16; o > 0; o >>= 1) {
        sum += __shfl_xor_sync(0xffffffffu, sum, o);
        sq  += __shfl_xor_sync(0xffffffffu, sq,  o);
    }
    __shared__ float ssum[4], ssq[4];
    int warp = t >> 5, lane = t & 31;
    if (lane == 0) { ssum[warp] = sum; ssq[warp] = sq; }
    __syncthreads();
    float tot = ssum[0] + ssum[1] + ssum[2] + ssum[3];
    float tq  = ssq[0]  + ssq[1]  + ssq[2]  + ssq[3];
    float mu  = tot * (1.0f / 512.0f);
    float var = tq * (1.0f / 512.0f) - mu * mu;
    float inv = rsqrtf(var + 1e-5f);
    float4 gg = ((const float4*)g)[t];
    float4 bb4 = ((const float4*)b)[t];
    float o0 = (v.x - mu) * inv * gg.x + bb4.x;
    float o1 = (v.y - mu) * inv * gg.y + bb4.y;
    float o2 = (v.z - mu) * inv * gg.z + bb4.z;
    float o3 = (v.w - mu) * inv * gg.w + bb4.w;

    size_t a0 = fragAddrH(r, 4 * t, 16);
    size_t a1 = fragAddrH(r, 4 * t + 2, 16);
    *(__half2*)&y[a0] = __floats2half2_rn(o0, o1);
    *(__half2*)&y[a1] = __floats2half2_rn(o2, o3);
}

// ---------------------------------------------------------------------------
// Windowed attention (fp32 SIMT, vectorized LDS). One block per (n, head).
// Row stride 36 floats (144B): 16B-aligned rows, consecutive rows hit distinct
// bank quads -> conflict-free lds.128. Lane key-set t = 4*tt + (tid&3).
// Writes ctx in half A-frag layout (kT=16).
// ---------------------------------------------------------------------------
__device__ __forceinline__ int regcode(int h) { return h < 56 ? 0 : (h < 60 ? 1 : 2); }

__global__ __launch_bounds__(256) void k_attn(const __half* __restrict__ qkv,
                                              __half* __restrict__ ctx)
{
    int n  = blockIdx.x >> 4;
    int hd = blockIdx.x & 15;

    __shared__ float sq[64][36], sk[64][36], sv[64][36];
    __shared__ float sp[64][68];

    int tid = threadIdx.x;
    for (int idx = tid; idx < 1024; idx += 256) {
        int s = idx >> 4, dd = (idx & 15) * 2;
        size_t base = ((size_t)(s * 2048 + n)) * 1536 + hd * 96 + dd;
        float2 q2 = __half22float2(*(const __half2*)&qkv[base]);
        float2 k2 = __half22float2(*(const __half2*)&qkv[base + 32]);
        float2 v2 = __half22float2(*(const __half2*)&qkv[base + 64]);
        sq[s][dd] = q2.x; sq[s][dd + 1] = q2.y;
        sk[s][dd] = k2.x; sk[s][dd + 1] = k2.y;
        sv[s][dd] = v2.x; sv[s][dd + 1] = v2.y;
    }
    __syncthreads();

    const int nw = n & 63;
    const int s  = tid >> 2;
    const int ql = tid & 3;
    const int hn8 = (nw >> 3) << 3;
    const int wn8 = (nw & 7) << 3;

    // Q row into registers (8 x lds.128, conflict-free: 8 rows x 144B)
    float4 qr[8];
    {
        const float4* sqv = (const float4*)&sq[s][0];
        #pragma unroll
        for (int j = 0; j < 8; j++) qr[j] = sqv[j];
    }

    const int cs = regcode(hn8 + (s >> 3)) * 3 + regcode(wn8 + (s & 7));

    float sc[16];
    float mx = -1e30f;
    #pragma unroll
    for (int tt = 0; tt < 16; tt++) {
        int t = (tt << 2) + ql;
        const float4* kv = (const float4*)&sk[t][0];
        float a = 0.0f;
        #pragma unroll
        for (int j = 0; j < 8; j++) {
            float4 kk = kv[j];
            a += qr[j].x * kk.x + qr[j].y * kk.y + qr[j].z * kk.z + qr[j].w * kk.w;
        }
        a *= 0.17677669529663689f;   // 1/sqrt(32)
        int ct = regcode(hn8 + (t >> 3)) * 3 + regcode(wn8 + (t & 7));
        a = (ct != cs) ? -10000.0f : a;
        sc[tt] = a;
        mx = fmaxf(mx, a);
    }
    mx = fmaxf(mx, __shfl_xor_sync(0xffffffffu, mx, 1));
    mx = fmaxf(mx, __shfl_xor_sync(0xffffffffu, mx, 2));
    float sum = 0.0f;
    #pragma unroll
    for (int tt = 0; tt < 16; tt++) { sc[tt] = __expf(sc[tt] - mx); sum += sc[tt]; }
    sum += __shfl_xor_sync(0xffffffffu, sum, 1);
    sum += __shfl_xor_sync(0xffffffffu, sum, 2);
    float inv = 1.0f / sum;
    #pragma unroll
    for (int tt = 0; tt < 16; tt++) sp[s][(tt << 2) + ql] = sc[tt] * inv;
    __syncthreads();

    // PV: each lane owns channels d0..d0+7, vectorized V reads (broadcast rows)
    const int d0 = ql * 8;
    float acc[8];
    #pragma unroll
    for (int d = 0; d < 8; d++) acc[d] = 0.0f;
    for (int t = 0; t < 64; t++) {
        float p = sp[s][t];
        const float4* vv = (const float4*)&sv[t][d0];
        float4 v0 = vv[0], v1 = vv[1];
        acc[0] += p * v0.x; acc[1] += p * v0.y; acc[2] += p * v0.z; acc[3] += p * v0.w;
        acc[4] += p * v1.x; acc[5] += p * v1.y; acc[6] += p * v1.z; acc[7] += p * v1.w;
    }

    long r = (long)s * 2048 + n;
    int cb = hd * 32 + d0;
    #pragma unroll
    for (int ii = 0; ii < 4; ii++) {
        size_t a = fragAddrH(r, cb + 2 * ii, 16);
        *(__half2*)&ctx[a] = __floats2half2_rn(acc[2 * ii], acc[2 * ii + 1]);
    }
}

// ---------------------------------------------------------------------------
// fp16 mma.sync GEMM: CTA tile 256x128, chunk K=32, 8 warps (4m x 2n) of 64x64.
//   EPI 0: half row-major out = acc + bias                     (QKV, Nout=1536)
//   EPI 1: scatter fp32: C[dest]=acc+bias+xwfrag[r]+hs[dest]   (proj)
//   EPI 2: half frag out (kT=64) = gelu(acc + bias)            (FC1)
//   EPI 3: fp32 row-major out = acc+bias+hidden[r]+ln2frag[r]  (FC2 final)
// ---------------------------------------------------------------------------
#define NSTAGE     4
#define STAGE_B    24576                 // 16KB A + 8KB B
#define DYN_SMEM   (NSTAGE * STAGE_B)    // 98304

template <int EPI>
__global__ __launch_bounds__(256, 1) void gemm_tc(const __half* __restrict__ A,
                                                  const __half* __restrict__ Bprep,
                                                  const float* __restrict__ bias,
                                                  void* __restrict__ Cout,
                                                  const void* __restrict__ add1,
                                                  const void* __restrict__ add2,
                                                  int Nout, int kTiles)
{
    extern __shared__ char smem[];
    const uint32_t sbase = smem_u32(smem);
    const int tid  = threadIdx.x;
    const int wid  = tid >> 5;
    const int lane = tid & 31;
    const int wm   = wid >> 1;
    const int wnb  = wid & 1;

    const long rowBlk = (long)blockIdx.y * 256;
    const int  colBlk = blockIdx.x * 128;
    const __half* Ablk = A + (size_t)blockIdx.y * kTiles * 8192;
    const __half* Bblk = Bprep + (size_t)blockIdx.x * kTiles * 4096;

    float acc[4][8][4];
    #pragma unroll
    for (int mi = 0; mi < 4; mi++)
        #pragma unroll
        for (int nt = 0; nt < 8; nt++)
            #pragma unroll
            for (int j = 0; j < 4; j++) acc[mi][nt][j] = 0.0f;

    auto issue = [&](int kt) {
        uint32_t aB = sbase + (kt % NSTAGE) * STAGE_B;
        uint32_t bB = aB + 16384;
        const __half* as = Ablk + (size_t)kt * 8192;
        const __half* bs = Bblk + (size_t)kt * 4096;
        #pragma unroll
        for (int i = 0; i < 4; i++)
            cp_async16(aB + (uint32_t)(tid + i * 256) * 16, as + (size_t)(tid + i * 256) * 8);
        #pragma unroll
        for (int i = 0; i < 2; i++)
            cp_async16(bB + (uint32_t)(tid + i * 256) * 16, bs + (size_t)(tid + i * 256) * 8);
        CP_COMMIT();
    };

    issue(0); issue(1); issue(2);

    for (int kt = 0; kt < kTiles; kt++) {
        if (kt < kTiles - 2)      { CP_WAIT(2); }
        else if (kt == kTiles - 2){ CP_WAIT(1); }
        else                      { CP_WAIT(0); }
        __syncthreads();
        if (kt + 3 < kTiles) issue(kt + 3);

        const uint32_t aB = sbase + (kt % NSTAGE) * STAGE_B;
        const uint32_t bB = aB + 16384;

        uint32_t bfr[8][4];
        #pragma unroll
        for (int nt = 0; nt < 8; nt++) {
            uint32_t addr = bB + (uint32_t)(((wnb * 8 + nt) * 32 + lane) * 16);
            asm volatile("ld.shared.v4.b32 {%0,%1,%2,%3}, [%4];"
                         : "=r"(bfr[nt][0]), "=r"(bfr[nt][1]), "=r"(bfr[nt][2]), "=r"(bfr[nt][3])
                         : "r"(addr));
        }
        #pragma unroll
        for (int ks2 = 0; ks2 < 2; ks2++) {
            uint32_t afr[4][4];
            #pragma unroll
            for (int mi = 0; mi < 4; mi++) {
                uint32_t addr = aB + (uint32_t)((((wm * 4 + mi) * 2 + ks2) * 32 + lane) * 16);
                asm volatile("ld.shared.v4.b32 {%0,%1,%2,%3}, [%4];"
                             : "=r"(afr[mi][0]), "=r"(afr[mi][1]), "=r"(afr[mi][2]), "=r"(afr[mi][3])
                             : "r"(addr));
            }
            #pragma unroll
            for (int mi = 0; mi < 4; mi++)
                #pragma unroll
                for (int nt = 0; nt < 8; nt++)
                    mma_f16(acc[mi][nt], afr[mi][0], afr[mi][1], afr[mi][2], afr[mi][3],
                            bfr[nt][ks2 * 2], bfr[nt][ks2 * 2 + 1]);
        }
    }

    const int g  = lane >> 2;
    const int q2 = lane & 3;

    float2 bs2[8];
    #pragma unroll
    for (int nt = 0; nt < 8; nt++)
        bs2[nt] = *(const float2*)&bias[colBlk + wnb * 64 + nt * 8 + q2 * 2];

    #pragma unroll
    for (int mi = 0; mi < 4; mi++) {
        long r = rowBlk + wm * 64 + mi * 16 + g;

        long d0 = 0, d1 = 0;
        if (EPI == 1) {
            {
                int s = (int)(r >> 11), n = (int)(r & 2047);
                int hn = s >> 3, wn2 = s & 7;
                int ij = n >> 5, b2 = n & 31;
                int h = ((hn << 3) + (ij >> 3) + 4) & 63;
                int w = ((wn2 << 3) + (ij & 7) + 4) & 63;
                d0 = ((long)(((h << 6) + w) * 32 + b2)) * 512;
            }
            {
                long r8 = r + 8;
                int s = (int)(r8 >> 11), n = (int)(r8 & 2047);
                int hn = s >> 3, wn2 = s & 7;
                int ij = n >> 5, b2 = n & 31;
                int h = ((hn << 3) + (ij >> 3) + 4) & 63;
                int w = ((wn2 << 3) + (ij & 7) + 4) & 63;
                d1 = ((long)(((h << 6) + w) * 32 + b2)) * 512;
            }
        }

        #pragma unroll
        for (int nt = 0; nt < 8; nt++) {
            int c = colBlk + wnb * 64 + nt * 8 + q2 * 2;
            float v00 = acc[mi][nt][0] + bs2[nt].x;
            float v01 = acc[mi][nt][1] + bs2[nt].y;
            float v10 = acc[mi][nt][2] + bs2[nt].x;
            float v11 = acc[mi][nt][3] + bs2[nt].y;

            if (EPI == 0) {
                __half* Ch = (__half*)Cout;
                *(__half2*)&Ch[r * Nout + c]       = __floats2half2_rn(v00, v01);
                *(__half2*)&Ch[(r + 8) * Nout + c] = __floats2half2_rn(v10, v11);
            } else if (EPI == 1) {
                float* Cf = (float*)Cout;
                const __half* xwH = (const __half*)add1;
                const float*  hsF = (const float*)add2;
                size_t a = fragAddrH(r, c, 16);
                float2 x01 = __half22float2(*(const __half2*)&xwH[a]);
                float2 x89 = __half22float2(*(const __half2*)&xwH[a + 2]);
                float2 s0 = *(const float2*)&hsF[d0 + c];
                float2 s1 = *(const float2*)&hsF[d1 + c];
                v00 += x01.x + s0.x; v01 += x01.y + s0.y;
                v10 += x89.x + s1.x; v11 += x89.y + s1.y;
                *(float2*)&Cf[d0 + c] = make_float2(v00, v01);
                *(float2*)&Cf[d1 + c] = make_float2(v10, v11);
            } else if (EPI == 2) {
                __half* Ch = (__half*)Cout;
                size_t a = fragAddrH(r, c, 64);
                *(__half2*)&Ch[a]     = __floats2half2_rn(gelu_exact(v00), gelu_exact(v01));
                *(__half2*)&Ch[a + 2] = __floats2half2_rn(gelu_exact(v10), gelu_exact(v11));
            } else {
                float* Cf = (float*)Cout;
                const float*  hF  = (const float*)add1;
                const __half* lnH = (const __half*)add2;
                size_t a = fragAddrH(r, c, 16);
                float2 l01 = __half22float2(*(const __half2*)&lnH[a]);
                float2 l89 = __half22float2(*(const __half2*)&lnH[a + 2]);
                float2 h0 = *(const float2*)&hF[r * 512 + c];
                float2 h1 = *(const float2*)&hF[(r + 8) * 512 + c];
                v00 += h0.x + l01.x; v01 += h0.y + l01.y;
                v10 += h1.x + l89.x; v11 += h1.y + l89.y;
                *(float2*)&Cf[r * 512 + c]       = make_float2(v00, v01);
                *(float2*)&Cf[(r + 8) * 512 + c] = make_float2(v10, v11);
            }
        }
    }
}

// ---------------------------------------------------------------------------
// Launcher
// ---------------------------------------------------------------------------
extern "C" void kernel_launch(void* const* d_in, const int* in_sizes, int n_in,
                              void* d_out, int out_size)
{
    const float* hs    = (const float*)d_in[0];
    const float* ln1g  = (const float*)d_in[1];
    const float* ln1b  = (const float*)d_in[2];
    const float* wqkv  = (const float*)d_in[3];
    const float* bqkv  = (const float*)d_in[4];
    const float* wproj = (const float*)d_in[5];
    const float* bproj = (const float*)d_in[6];
    const float* ln2g  = (const float*)d_in[7];
    const float* ln2b  = (const float*)d_in[8];
    const float* wfc1  = (const float*)d_in[9];
    const float* bfc1  = (const float*)d_in[10];
    const float* wfc2  = (const float*)d_in[11];
    const float* bfc2  = (const float*)d_in[12];
    float* out = (float*)d_out;

    __half *xw, *ctx, *ln2buf, *big, *wprep;
    float *hidden;
    cudaGetSymbolAddress((void**)&xw,     g_xw);
    cudaGetSymbolAddress((void**)&ctx,    g_ctx);
    cudaGetSymbolAddress((void**)&hidden, g_hidden);
    cudaGetSymbolAddress((void**)&ln2buf, g_ln2);
    cudaGetSymbolAddress((void**)&big,    g_big);
    cudaGetSymbolAddress((void**)&wprep,  g_wprep);

    static int smem_set = 0;
    if (!smem_set) {
        cudaFuncSetAttribute(gemm_tc<0>, cudaFuncAttributeMaxDynamicSharedMemorySize, DYN_SMEM);
        cudaFuncSetAttribute(gemm_tc<1>, cudaFuncAttributeMaxDynamicSharedMemorySize, DYN_SMEM);
        cudaFuncSetAttribute(gemm_tc<2>, cudaFuncAttributeMaxDynamicSharedMemorySize, DYN_SMEM);
        cudaFuncSetAttribute(gemm_tc<3>, cudaFuncAttributeMaxDynamicSharedMemorySize, DYN_SMEM);
        smem_set = 1;
    }

    // 0) preformat weights into half B-fragment blocks
    k_prep<<<dim3(12, 16), 256>>>(wqkv,  wprep + WP_QKV,  1536, 16);
    k_prep<<<dim3(4,  16), 256>>>(wproj, wprep + WP_PROJ, 512,  16);
    k_prep<<<dim3(16, 16), 256>>>(wfc1,  wprep + WP_FC1,  2048, 16);
    k_prep<<<dim3(4,  64), 256>>>(wfc2,  wprep + WP_FC2,  512,  64);

    // 1) LN1 + shift + window partition -> xw (half frag)
    k_ln<<<MROWS, 128>>>(hs, ln1g, ln1b, xw, 1);

    // 2) QKV GEMM -> big (half row-major, 1536)
    gemm_tc<0><<<dim3(12, 512), 256, DYN_SMEM>>>(xw, wprep + WP_QKV, bqkv, big,
                                                 nullptr, nullptr, 1536, 16);

    // 3) Windowed attention (vectorized SIMT) -> ctx (half frag)
    k_attn<<<2048 * 16, 256>>>(big, ctx);

    // 4) Proj GEMM + residual + window-reverse scatter -> hidden (fp32 row-major)
    gemm_tc<1><<<dim3(4, 512), 256, DYN_SMEM>>>(ctx, wprep + WP_PROJ, bproj, hidden,
                                                xw, hs, 512, 16);

    // 5) LN2 -> ln2buf (half frag)
    k_ln<<<MROWS, 128>>>(hidden, ln2g, ln2b, ln2buf, 0);

    // 6) FC1 GEMM + GELU -> big (half frag, kT=64)
    gemm_tc<2><<<dim3(16, 512), 256, DYN_SMEM>>>(ln2buf, wprep + WP_FC1, bfc1, big,
                                                 nullptr, nullptr, 2048, 16);

    // 7) FC2 GEMM + final residuals -> out (fp32 row-major)
    gemm_tc<3><<<dim3(4, 512), 256, DYN_SMEM>>>(big, wprep + WP_FC2, bfc2, out,
                                                hidden, ln2buf, 512, 64);
}

// round 12
// speedup vs baseline: 1.4640x; 1.1863x over previous
#include <cuda_runtime.h>
#include <cuda_fp16.h>
#include <math.h>
#include <stdint.h>

// ---------------------------------------------------------------------------
// Problem constants
// ---------------------------------------------------------------------------
#define CSZ     512
#define MROWS   131072      // H*W*B = 4096*32

// ---------------------------------------------------------------------------
// Scratch (static device globals -- no allocations allowed)
// ---------------------------------------------------------------------------
__device__ __half g_xw    [(size_t)MROWS * CSZ];    // LN1 out, A-frag half (kT=16)
__device__ __half g_ctx   [(size_t)MROWS * CSZ];    // attn out, A-frag half (kT=16)
__device__ float  g_hidden[(size_t)MROWS * CSZ];    // post-attn residual, row-major fp32
__device__ __half g_ln2   [(size_t)MROWS * CSZ];    // LN2 out, A-frag half (kT=16)
__device__ __half g_big   [(size_t)MROWS * 2048];   // qkv row-major half(1536); fc1-out frag (kT=64)
__device__ __half g_wprep [512*1536 + 512*512 + 512*2048 + 2048*512];

#define WP_QKV  0
#define WP_PROJ (512*1536)
#define WP_FC1  (WP_PROJ + 512*512)
#define WP_FC2  (WP_FC1 + 512*2048)

// ---------------------------------------------------------------------------
// Helpers
// ---------------------------------------------------------------------------
__device__ __forceinline__ uint32_t smem_u32(const void* p) {
    uint32_t a;
    asm("{ .reg .u64 t; cvta.to.shared.u64 t, %1; cvt.u32.u64 %0, t; }" : "=r"(a) : "l"(p));
    return a;
}
__device__ __forceinline__ void mma_f16(float* d, uint32_t a0, uint32_t a1, uint32_t a2, uint32_t a3,
                                        uint32_t b0, uint32_t b1)
{
    asm volatile(
        "mma.sync.aligned.m16n8k16.row.col.f32.f16.f16.f32 "
        "{%0,%1,%2,%3}, {%4,%5,%6,%7}, {%8,%9}, {%0,%1,%2,%3};"
        : "+f"(d[0]), "+f"(d[1]), "+f"(d[2]), "+f"(d[3])
        : "r"(a0), "r"(a1), "r"(a2), "r"(a3), "r"(b0), "r"(b1));
}
__device__ __forceinline__ void cp_async16(uint32_t dst, const void* src) {
    asm volatile("cp.async.cg.shared.global [%0], [%1], 16;" :: "r"(dst), "l"(src) : "memory");
}
#define CP_COMMIT() asm volatile("cp.async.commit_group;" ::: "memory")
#define CP_WAIT(n)  asm volatile("cp.async.wait_group %0;" :: "n"(n) : "memory")

__device__ __forceinline__ float gelu_exact(float x)
{
    return 0.5f * x * (1.0f + erff(x * 0.70710678118654752f));
}

// Half A-fragment address (half index) for element (row r, channel c), kT chunks.
__device__ __forceinline__ size_t fragAddrH(long r, int c, int kT) {
    int rm = (int)(r & 255);
    int ri = rm & 15;
    int k  = c & 31;
    return ((size_t)(r >> 8) * kT + (c >> 5)) * 8192
         + (size_t)(((((rm >> 4) * 2 + (k >> 4)) * 32) + (ri & 7) * 4 + ((k >> 1) & 3)) * 8
         + ((k >> 3) & 1) * 4 + (ri >> 3) * 2 + (k & 1));
}

// ---------------------------------------------------------------------------
// Weight prep: W[K,N] fp32 row-major -> per (ntile j, kchunk kt) 4096-half B-frag
// ---------------------------------------------------------------------------
__global__ __launch_bounds__(256) void k_prep(const float* __restrict__ W,
                                              __half* __restrict__ dst,
                                              int N, int kTiles)
{
    int j = blockIdx.x, kt = blockIdx.y;
    __half* blk = dst + ((size_t)(j * kTiles + kt)) * 4096;
    for (int f = threadIdx.x; f < 4096; f += 256) {
        int klo = f & 1;
        int reg = (f >> 1) & 3;
        int lanep = (f >> 3) & 31;
        int q = lanep & 3, g = lanep >> 2;
        int nt = f >> 8;
        int n_local = nt * 8 + g;
        int k_local = reg * 8 + q * 2 + klo;
        blk[f] = __float2half_rn(W[(size_t)(kt * 32 + k_local) * N + j * 128 + n_local]);
    }
}

// ---------------------------------------------------------------------------
// LayerNorm (+ optional shift/window-partition gather); writes half A-frag (kT=16)
// ---------------------------------------------------------------------------
__global__ __launch_bounds__(128) void k_ln(const float* __restrict__ x,
                                            const float* __restrict__ g,
                                            const float* __restrict__ b,
                                            __half* __restrict__ y,
                                            int permute)
{
    long r = blockIdx.x;
    long src = r;
    if (permute) {
        int s  = (int)(r >> 11), n = (int)(r & 2047);
        int hn = s >> 3, wn = s & 7;
        int ij = n >> 5, bb = n & 31;
        int h  = ((hn << 3) + (ij >> 3) + 4) & 63;
        int w  = ((wn << 3) + (ij & 7) + 4) & 63;
        src = ((h << 6) + w) * 32 + bb;
    }
    int t = threadIdx.x;
    float4 v = ((const float4*)(x + src * CSZ))[t];
    float sum = v.x + v.y + v.z + v.w;
    float sq  = v.x*v.x + v.y*v.y + v.z*v.z + v.w*v.w;
    #pragma unroll
    for (int o = 16; o > 0; o >>= 1) {
        sum += __shfl_xor_sync(0xffffffffu, sum, o);
        sq  += __shfl_xor_sync(0xffffffffu, sq,  o);
    }
    __shared__ float ssum[4], ssq[4];
    int warp = t >> 5, lane = t & 31;
    if (lane == 0) { ssum[warp] = sum; ssq[warp] = sq; }
    __syncthreads();
    float tot = ssum[0] + ssum[1] + ssum[2] + ssum[3];
    float tq  = ssq[0]  + ssq[1]  + ssq[2]  + ssq[3];
    float mu  = tot * (1.0f / 512.0f);
    float var = tq * (1.0f / 512.0f) - mu * mu;
    float inv = rsqrtf(var + 1e-5f);
    float4 gg = ((const float4*)g)[t];
    float4 bb4 = ((const float4*)b)[t];
    float o0 = (v.x - mu) * inv * gg.x + bb4.x;
    float o1 = (v.y - mu) * inv * gg.y + bb4.y;
    float o2 = (v.z - mu) * inv * gg.z + bb4.z;
    float o3 = (v.w - mu) * inv * gg.w + bb4.w;

    size_t a0 = fragAddrH(r, 4 * t, 16);
    size_t a1 = fragAddrH(r, 4 * t + 2, 16);
    *(__half2*)&y[a0] = __floats2half2_rn(o0, o1);
    *(__half2*)&y[a1] = __floats2half2_rn(o2, o3);
}

// ---------------------------------------------------------------------------
// Windowed attention (fp32 SIMT, vectorized LDS). One block per (n, head).
// ---------------------------------------------------------------------------
__device__ __forceinline__ int regcode(int h) { return h < 56 ? 0 : (h < 60 ? 1 : 2); }

__global__ __launch_bounds__(256) void k_attn(const __half* __restrict__ qkv,
                                              __half* __restrict__ ctx)
{
    int n  = blockIdx.x >> 4;
    int hd = blockIdx.x & 15;

    __shared__ float sq[64][36], sk[64][36], sv[64][36];
    __shared__ float sp[64][68];

    int tid = threadIdx.x;
    for (int idx = tid; idx < 1024; idx += 256) {
        int s = idx >> 4, dd = (idx & 15) * 2;
        size_t base = ((size_t)(s * 2048 + n)) * 1536 + hd * 96 + dd;
        float2 q2 = __half22float2(*(const __half2*)&qkv[base]);
        float2 k2 = __half22float2(*(const __half2*)&qkv[base + 32]);
        float2 v2 = __half22float2(*(const __half2*)&qkv[base + 64]);
        sq[s][dd] = q2.x; sq[s][dd + 1] = q2.y;
        sk[s][dd] = k2.x; sk[s][dd + 1] = k2.y;
        sv[s][dd] = v2.x; sv[s][dd + 1] = v2.y;
    }
    __syncthreads();

    const int nw = n & 63;
    const int s  = tid >> 2;
    const int ql = tid & 3;
    const int hn8 = (nw >> 3) << 3;
    const int wn8 = (nw & 7) << 3;

    float4 qr[8];
    {
        const float4* sqv = (const float4*)&sq[s][0];
        #pragma unroll
        for (int j = 0; j < 8; j++) qr[j] = sqv[j];
    }

    const int cs = regcode(hn8 + (s >> 3)) * 3 + regcode(wn8 + (s & 7));

    float sc[16];
    float mx = -1e30f;
    #pragma unroll
    for (int tt = 0; tt < 16; tt++) {
        int t = (tt << 2) + ql;
        const float4* kv = (const float4*)&sk[t][0];
        float a = 0.0f;
        #pragma unroll
        for (int j = 0; j < 8; j++) {
            float4 kk = kv[j];
            a += qr[j].x * kk.x + qr[j].y * kk.y + qr[j].z * kk.z + qr[j].w * kk.w;
        }
        a *= 0.17677669529663689f;
        int ct = regcode(hn8 + (t >> 3)) * 3 + regcode(wn8 + (t & 7));
        a = (ct != cs) ? -10000.0f : a;
        sc[tt] = a;
        mx = fmaxf(mx, a);
    }
    mx = fmaxf(mx, __shfl_xor_sync(0xffffffffu, mx, 1));
    mx = fmaxf(mx, __shfl_xor_sync(0xffffffffu, mx, 2));
    float sum = 0.0f;
    #pragma unroll
    for (int tt = 0; tt < 16; tt++) { sc[tt] = __expf(sc[tt] - mx); sum += sc[tt]; }
    sum += __shfl_xor_sync(0xffffffffu, sum, 1);
    sum += __shfl_xor_sync(0xffffffffu, sum, 2);
    float inv = 1.0f / sum;
    #pragma unroll
    for (int tt = 0; tt < 16; tt++) sp[s][(tt << 2) + ql] = sc[tt] * inv;
    __syncthreads();

    const int d0 = ql * 8;
    float acc[8];
    #pragma unroll
    for (int d = 0; d < 8; d++) acc[d] = 0.0f;
    for (int t = 0; t < 64; t++) {
        float p = sp[s][t];
        const float4* vv = (const float4*)&sv[t][d0];
        float4 v0 = vv[0], v1 = vv[1];
        acc[0] += p * v0.x; acc[1] += p * v0.y; acc[2] += p * v0.z; acc[3] += p * v0.w;
        acc[4] += p * v1.x; acc[5] += p * v1.y; acc[6] += p * v1.z; acc[7] += p * v1.w;
    }

    long r = (long)s * 2048 + n;
    int cb = hd * 32 + d0;
    #pragma unroll
    for (int ii = 0; ii < 4; ii++) {
        size_t a = fragAddrH(r, cb + 2 * ii, 16);
        *(__half2*)&ctx[a] = __floats2half2_rn(acc[2 * ii], acc[2 * ii + 1]);
    }
}

// ---------------------------------------------------------------------------
// fp16 mma.sync GEMM: CTA tile 128x128 (4 warps of 64x64), chunk K=32.
// 128-thread CTAs -> 2 CTAs/SM so per-CTA barriers/waits overlap across CTAs.
// A-frag blocks are mt-major, so a 128-row CTA reads a contiguous 4096-half
// sub-block: base = (row256*kT + kt)*8192 + sub*4096.
//   EPI 0: half row-major out = acc + bias                     (QKV, Nout=1536)
//   EPI 1: scatter fp32: C[dest]=acc+bias+xwfrag[r]+hs[dest]   (proj)
//   EPI 2: half frag out (kT=64) = gelu(acc + bias)            (FC1)
//   EPI 3: fp32 row-major out = acc+bias+hidden[r]+ln2frag[r]  (FC2 final)
// ---------------------------------------------------------------------------
#define NSTAGE     4
#define STAGE_B    16384                 // 8KB A + 8KB B
#define DYN_SMEM   (NSTAGE * STAGE_B)    // 65536

template <int EPI>
__global__ __launch_bounds__(128, 2) void gemm_tc(const __half* __restrict__ A,
                                                  const __half* __restrict__ Bprep,
                                                  const float* __restrict__ bias,
                                                  void* __restrict__ Cout,
                                                  const void* __restrict__ add1,
                                                  const void* __restrict__ add2,
                                                  int Nout, int kTiles)
{
    extern __shared__ char smem[];
    const uint32_t sbase = smem_u32(smem);
    const int tid  = threadIdx.x;
    const int wid  = tid >> 5;
    const int lane = tid & 31;
    const int wm   = wid >> 1;   // 0..1 (64-row band)
    const int wnb  = wid & 1;    // 0..1 (64-col band)

    const long rowBlk = (long)blockIdx.y * 128;
    const int  colBlk = blockIdx.x * 128;
    // contiguous 4096-half sub-block of each (256-row, kt) A block
    const __half* Ablk = A + ((size_t)(blockIdx.y >> 1) * kTiles) * 8192
                           + (size_t)(blockIdx.y & 1) * 4096;
    const __half* Bblk = Bprep + (size_t)blockIdx.x * kTiles * 4096;

    float acc[4][8][4];
    #pragma unroll
    for (int mi = 0; mi < 4; mi++)
        #pragma unroll
        for (int nt = 0; nt < 8; nt++)
            #pragma unroll
            for (int j = 0; j < 4; j++) acc[mi][nt][j] = 0.0f;

    auto issue = [&](int kt) {
        uint32_t aB = sbase + (kt % NSTAGE) * STAGE_B;
        uint32_t bB = aB + 8192;
        const __half* as = Ablk + (size_t)kt * 8192;
        const __half* bs = Bblk + (size_t)kt * 4096;
        #pragma unroll
        for (int i = 0; i < 4; i++)
            cp_async16(aB + (uint32_t)(tid + i * 128) * 16, as + (size_t)(tid + i * 128) * 8);
        #pragma unroll
        for (int i = 0; i < 4; i++)
            cp_async16(bB + (uint32_t)(tid + i * 128) * 16, bs + (size_t)(tid + i * 128) * 8);
        CP_COMMIT();
    };

    issue(0); issue(1); issue(2);

    for (int kt = 0; kt < kTiles; kt++) {
        if (kt < kTiles - 2)      { CP_WAIT(2); }
        else if (kt == kTiles - 2){ CP_WAIT(1); }
        else                      { CP_WAIT(0); }
        __syncthreads();
        if (kt + 3 < kTiles) issue(kt + 3);

        const uint32_t aB = sbase + (kt % NSTAGE) * STAGE_B;
        const uint32_t bB = aB + 8192;

        uint32_t bfr[8][4];
        #pragma unroll
        for (int nt = 0; nt < 8; nt++) {
            uint32_t addr = bB + (uint32_t)(((wnb * 8 + nt) * 32 + lane) * 16);
            asm volatile("ld.shared.v4.b32 {%0,%1,%2,%3}, [%4];"
                         : "=r"(bfr[nt][0]), "=r"(bfr[nt][1]), "=r"(bfr[nt][2]), "=r"(bfr[nt][3])
                         : "r"(addr));
        }
        #pragma unroll
        for (int ks2 = 0; ks2 < 2; ks2++) {
            uint32_t afr[4][4];
            #pragma unroll
            for (int mi = 0; mi < 4; mi++) {
                uint32_t addr = aB + (uint32_t)((((wm * 4 + mi) * 2 + ks2) * 32 + lane) * 16);
                asm volatile("ld.shared.v4.b32 {%0,%1,%2,%3}, [%4];"
                             : "=r"(afr[mi][0]), "=r"(afr[mi][1]), "=r"(afr[mi][2]), "=r"(afr[mi][3])
                             : "r"(addr));
            }
            #pragma unroll
            for (int mi = 0; mi < 4; mi++)
                #pragma unroll
                for (int nt = 0; nt < 8; nt++)
                    mma_f16(acc[mi][nt], afr[mi][0], afr[mi][1], afr[mi][2], afr[mi][3],
                            bfr[nt][ks2 * 2], bfr[nt][ks2 * 2 + 1]);
        }
    }

    const int g  = lane >> 2;
    const int q2 = lane & 3;

    float2 bs2[8];
    #pragma unroll
    for (int nt = 0; nt < 8; nt++)
        bs2[nt] = *(const float2*)&bias[colBlk + wnb * 64 + nt * 8 + q2 * 2];

    #pragma unroll
    for (int mi = 0; mi < 4; mi++) {
        long r = rowBlk + wm * 64 + mi * 16 + g;

        long d0 = 0, d1 = 0;
        if (EPI == 1) {
            {
                int s = (int)(r >> 11), n = (int)(r & 2047);
                int hn = s >> 3, wn2 = s & 7;
                int ij = n >> 5, b2 = n & 31;
                int h = ((hn << 3) + (ij >> 3) + 4) & 63;
                int w = ((wn2 << 3) + (ij & 7) + 4) & 63;
                d0 = ((long)(((h << 6) + w) * 32 + b2)) * 512;
            }
            {
                long r8 = r + 8;
                int s = (int)(r8 >> 11), n = (int)(r8 & 2047);
                int hn = s >> 3, wn2 = s & 7;
                int ij = n >> 5, b2 = n & 31;
                int h = ((hn << 3) + (ij >> 3) + 4) & 63;
                int w = ((wn2 << 3) + (ij & 7) + 4) & 63;
                d1 = ((long)(((h << 6) + w) * 32 + b2)) * 512;
            }
        }

        #pragma unroll
        for (int nt = 0; nt < 8; nt++) {
            int c = colBlk + wnb * 64 + nt * 8 + q2 * 2;
            float v00 = acc[mi][nt][0] + bs2[nt].x;
            float v01 = acc[mi][nt][1] + bs2[nt].y;
            float v10 = acc[mi][nt][2] + bs2[nt].x;
            float v11 = acc[mi][nt][3] + bs2[nt].y;

            if (EPI == 0) {
                __half* Ch = (__half*)Cout;
                *(__half2*)&Ch[r * Nout + c]       = __floats2half2_rn(v00, v01);
                *(__half2*)&Ch[(r + 8) * Nout + c] = __floats2half2_rn(v10, v11);
            } else if (EPI == 1) {
                float* Cf = (float*)Cout;
                const __half* xwH = (const __half*)add1;
                const float*  hsF = (const float*)add2;
                size_t a = fragAddrH(r, c, 16);
                float2 x01 = __half22float2(*(const __half2*)&xwH[a]);
                float2 x89 = __half22float2(*(const __half2*)&xwH[a + 2]);
                float2 s0 = *(const float2*)&hsF[d0 + c];
                float2 s1 = *(const float2*)&hsF[d1 + c];
                v00 += x01.x + s0.x; v01 += x01.y + s0.y;
                v10 += x89.x + s1.x; v11 += x89.y + s1.y;
                *(float2*)&Cf[d0 + c] = make_float2(v00, v01);
                *(float2*)&Cf[d1 + c] = make_float2(v10, v11);
            } else if (EPI == 2) {
                __half* Ch = (__half*)Cout;
                size_t a = fragAddrH(r, c, 64);
                *(__half2*)&Ch[a]     = __floats2half2_rn(gelu_exact(v00), gelu_exact(v01));
                *(__half2*)&Ch[a + 2] = __floats2half2_rn(gelu_exact(v10), gelu_exact(v11));
            } else {
                float* Cf = (float*)Cout;
                const float*  hF  = (const float*)add1;
                const __half* lnH = (const __half*)add2;
                size_t a = fragAddrH(r, c, 16);
                float2 l01 = __half22float2(*(const __half2*)&lnH[a]);
                float2 l89 = __half22float2(*(const __half2*)&lnH[a + 2]);
                float2 h0 = *(const float2*)&hF[r * 512 + c];
                float2 h1 = *(const float2*)&hF[(r + 8) * 512 + c];
                v00 += h0.x + l01.x; v01 += h0.y + l01.y;
                v10 += h1.x + l89.x; v11 += h1.y + l89.y;
                *(float2*)&Cf[r * 512 + c]       = make_float2(v00, v01);
                *(float2*)&Cf[(r + 8) * 512 + c] = make_float2(v10, v11);
            }
        }
    }
}

// ---------------------------------------------------------------------------
// Launcher
// ---------------------------------------------------------------------------
extern "C" void kernel_launch(void* const* d_in, const int* in_sizes, int n_in,
                              void* d_out, int out_size)
{
    const float* hs    = (const float*)d_in[0];
    const float* ln1g  = (const float*)d_in[1];
    const float* ln1b  = (const float*)d_in[2];
    const float* wqkv  = (const float*)d_in[3];
    const float* bqkv  = (const float*)d_in[4];
    const float* wproj = (const float*)d_in[5];
    const float* bproj = (const float*)d_in[6];
    const float* ln2g  = (const float*)d_in[7];
    const float* ln2b  = (const float*)d_in[8];
    const float* wfc1  = (const float*)d_in[9];
    const float* bfc1  = (const float*)d_in[10];
    const float* wfc2  = (const float*)d_in[11];
    const float* bfc2  = (const float*)d_in[12];
    float* out = (float*)d_out;

    __half *xw, *ctx, *ln2buf, *big, *wprep;
    float *hidden;
    cudaGetSymbolAddress((void**)&xw,     g_xw);
    cudaGetSymbolAddress((void**)&ctx,    g_ctx);
    cudaGetSymbolAddress((void**)&hidden, g_hidden);
    cudaGetSymbolAddress((void**)&ln2buf, g_ln2);
    cudaGetSymbolAddress((void**)&big,    g_big);
    cudaGetSymbolAddress((void**)&wprep,  g_wprep);

    static int smem_set = 0;
    if (!smem_set) {
        cudaFuncSetAttribute(gemm_tc<0>, cudaFuncAttributeMaxDynamicSharedMemorySize, DYN_SMEM);
        cudaFuncSetAttribute(gemm_tc<1>, cudaFuncAttributeMaxDynamicSharedMemorySize, DYN_SMEM);
        cudaFuncSetAttribute(gemm_tc<2>, cudaFuncAttributeMaxDynamicSharedMemorySize, DYN_SMEM);
        cudaFuncSetAttribute(gemm_tc<3>, cudaFuncAttributeMaxDynamicSharedMemorySize, DYN_SMEM);
        smem_set = 1;
    }

    // 0) preformat weights into half B-fragment blocks
    k_prep<<<dim3(12, 16), 256>>>(wqkv,  wprep + WP_QKV,  1536, 16);
    k_prep<<<dim3(4,  16), 256>>>(wproj, wprep + WP_PROJ, 512,  16);
    k_prep<<<dim3(16, 16), 256>>>(wfc1,  wprep + WP_FC1,  2048, 16);
    k_prep<<<dim3(4,  64), 256>>>(wfc2,  wprep + WP_FC2,  512,  64);

    // 1) LN1 + shift + window partition -> xw (half frag)
    k_ln<<<MROWS, 128>>>(hs, ln1g, ln1b, xw, 1);

    // 2) QKV GEMM -> big (half row-major, 1536)
    gemm_tc<0><<<dim3(12, 1024), 128, DYN_SMEM>>>(xw, wprep + WP_QKV, bqkv, big,
                                                  nullptr, nullptr, 1536, 16);

    // 3) Windowed attention (vectorized SIMT) -> ctx (half frag)
    k_attn<<<2048 * 16, 256>>>(big, ctx);

    // 4) Proj GEMM + residual + window-reverse scatter -> hidden (fp32 row-major)
    gemm_tc<1><<<dim3(4, 1024), 128, DYN_SMEM>>>(ctx, wprep + WP_PROJ, bproj, hidden,
                                                 xw, hs, 512, 16);

    // 5) LN2 -> ln2buf (half frag)
    k_ln<<<MROWS, 128>>>(hidden, ln2g, ln2b, ln2buf, 0);

    // 6) FC1 GEMM + GELU -> big (half frag, kT=64)
    gemm_tc<2><<<dim3(16, 1024), 128, DYN_SMEM>>>(ln2buf, wprep + WP_FC1, bfc1, big,
                                                  nullptr, nullptr, 2048, 16);

    // 7) FC2 GEMM + final residuals -> out (fp32 row-major)
    gemm_tc<3><<<dim3(4, 1024), 128, DYN_SMEM>>>(big, wprep + WP_FC2, bfc2, out,
                                                 hidden, ln2buf, 512, 64);
}